// round 1
// baseline (speedup 1.0000x reference)
#include <cuda_runtime.h>
#include <stdint.h>

#define B_  32
#define H_  512
#define W_  512
#define C_  4
#define PIX_PER_IMG (H_ * W_)          // 262144
#define CHUNKS 64                       // stage-1 blocks per batch
#define PIX_PER_CHUNK (PIX_PER_IMG / CHUNKS)   // 4096 pixels
#define F4_PER_CHUNK (PIX_PER_CHUNK / 4)       // 1024 float4 of mk

// Scratch (no allocations allowed)
__device__ float g_part[B_ * CHUNKS * 3];
__device__ int   g_shift[B_ * 2];       // (dx, dy) per batch

// ---------------------------------------------------------------------------
// Stage 1: per-chunk partial moments of mk.
// Deterministic: fixed per-thread sequential accumulation + fixed tree reduce.
// ---------------------------------------------------------------------------
__global__ __launch_bounds__(256) void moments_stage1(const float* __restrict__ mk)
{
    const int b     = blockIdx.y;
    const int chunk = blockIdx.x;       // 0..63
    const int t     = threadIdx.x;      // 0..255

    const float4* base =
        (const float4*)(mk + (size_t)b * PIX_PER_IMG) + chunk * F4_PER_CHUNK;

    float s0 = 0.f, s1 = 0.f, s2 = 0.f;
#pragma unroll
    for (int i = 0; i < F4_PER_CHUNK / 256; i++) {
        const int f4i = t + i * 256;                 // 0..1023
        const float4 v = base[f4i];
        const int p = chunk * PIX_PER_CHUNK + f4i * 4;  // flat pixel idx in image
        const int h = p >> 9;                        // /512
        const int w = p & (W_ - 1);                  // w, w+1, w+2, w+3 same row
        const float ry  = (float)(h - (H_ / 2));
        const float rx0 = (float)(w - (W_ / 2));
        const float sum = v.x + v.y + v.z + v.w;
        s0 += sum;
        s2 += ry * sum;
        s1 += rx0 * v.x + (rx0 + 1.f) * v.y + (rx0 + 2.f) * v.z + (rx0 + 3.f) * v.w;
    }

    __shared__ float sh0[256], sh1[256], sh2[256];
    sh0[t] = s0; sh1[t] = s1; sh2[t] = s2;
    __syncthreads();
#pragma unroll
    for (int st = 128; st > 0; st >>= 1) {
        if (t < st) {
            sh0[t] += sh0[t + st];
            sh1[t] += sh1[t + st];
            sh2[t] += sh2[t + st];
        }
        __syncthreads();
    }
    if (t == 0) {
        const int o = (b * CHUNKS + chunk) * 3;
        g_part[o + 0] = sh0[0];
        g_part[o + 1] = sh1[0];
        g_part[o + 2] = sh2[0];
    }
}

// ---------------------------------------------------------------------------
// Stage 2: reduce 64 partials per batch (deterministic tree) -> (dx, dy)
// ---------------------------------------------------------------------------
__global__ __launch_bounds__(64) void moments_stage2()
{
    const int b = blockIdx.x;
    const int t = threadIdx.x;          // 0..63

    __shared__ float sh0[64], sh1[64], sh2[64];
    const int o = (b * CHUNKS + t) * 3;
    sh0[t] = g_part[o + 0];
    sh1[t] = g_part[o + 1];
    sh2[t] = g_part[o + 2];
    __syncthreads();
#pragma unroll
    for (int st = 32; st > 0; st >>= 1) {
        if (t < st) {
            sh0[t] += sh0[t + st];
            sh1[t] += sh1[t + st];
            sh2[t] += sh2[t + st];
        }
        __syncthreads();
    }
    if (t == 0) {
        const float m00 = fmaxf(0.001f, sh0[0]);
        // rintf = round-half-even, matching jnp.round
        g_shift[b * 2 + 0] = (int)rintf(sh1[0] / m00);   // dx
        g_shift[b * 2 + 1] = (int)rintf(sh2[0] / m00);   // dy
    }
}

// ---------------------------------------------------------------------------
// Stage 3: shifted copy. One pixel (float4, 16B) per thread, coalesced.
// out[b,h,w] = x[b, h+dy, w+dx] if in-bounds else 0   (clamped-pad semantics)
// ---------------------------------------------------------------------------
__global__ __launch_bounds__(256) void shift_kernel(const float4* __restrict__ x,
                                                    float4* __restrict__ out)
{
    const int idx = blockIdx.x * 256 + threadIdx.x;  // pixel index 0..8388607
    const int b = idx >> 18;                         // / (H*W)
    const int p = idx & (PIX_PER_IMG - 1);
    const int h = p >> 9;
    const int w = p & (W_ - 1);

    const int dx = g_shift[b * 2 + 0];
    const int dy = g_shift[b * 2 + 1];
    const int sh = h + dy;
    const int sw = w + dx;

    float4 v = make_float4(0.f, 0.f, 0.f, 0.f);
    if ((unsigned)sh < (unsigned)H_ && (unsigned)sw < (unsigned)W_)
        v = x[(b << 18) + (sh << 9) + sw];
    out[idx] = v;
}

// ---------------------------------------------------------------------------
extern "C" void kernel_launch(void* const* d_in, const int* in_sizes, int n_in,
                              void* d_out, int out_size)
{
    const float* x  = (const float*)d_in[0];   // [32,512,512,4]
    const float* mk = (const float*)d_in[1];   // [32,512,512,1]
    float* out = (float*)d_out;

    dim3 g1(CHUNKS, B_);
    moments_stage1<<<g1, 256>>>(mk);
    moments_stage2<<<B_, 64>>>();

    const int total_pix = B_ * PIX_PER_IMG;    // 8388608
    shift_kernel<<<total_pix / 256, 256>>>((const float4*)x, (float4*)out);
}

// round 2
// speedup vs baseline: 1.0052x; 1.0052x over previous
#include <cuda_runtime.h>
#include <stdint.h>

#define B_  32
#define H_  512
#define W_  512
#define PIX_PER_IMG (H_ * W_)                    // 262144
#define CHUNKS 64                                // stage-1 blocks per batch
#define PIX_PER_CHUNK (PIX_PER_IMG / CHUNKS)     // 4096 pixels
#define F4_PER_CHUNK (PIX_PER_CHUNK / 4)         // 1024 float4 of mk

// Scratch (no allocations allowed)
__device__ float        g_part[B_ * CHUNKS * 3];
__device__ int          g_shift[B_ * 2];         // (dx, dy) per batch
__device__ unsigned int g_cnt[B_];               // zero-init; self-reset each launch

// ---------------------------------------------------------------------------
// Stage 1 (fused): per-chunk partial moments of mk + last-block finalize.
// Deterministic: fixed per-thread accumulation order, butterfly shuffle
// reduce (fixed order), and the finalize block reduces the 64 partials in a
// fixed tree order regardless of which block arrives last.
// ---------------------------------------------------------------------------
__global__ __launch_bounds__(256) void moments_fused(const float* __restrict__ mk)
{
    const int b     = blockIdx.y;
    const int chunk = blockIdx.x;       // 0..63
    const int t     = threadIdx.x;      // 0..255
    const int lane  = t & 31;
    const int wid   = t >> 5;           // 0..7

    const float4* base =
        (const float4*)(mk + (size_t)b * PIX_PER_IMG) + chunk * F4_PER_CHUNK;

    float s0 = 0.f, s1 = 0.f, s2 = 0.f;
#pragma unroll
    for (int i = 0; i < F4_PER_CHUNK / 256; i++) {
        const int f4i = t + i * 256;                    // 0..1023
        const float4 v = base[f4i];
        const int p = chunk * PIX_PER_CHUNK + f4i * 4;  // flat pixel idx in image
        const int h = p >> 9;
        const int w = p & (W_ - 1);
        const float ry  = (float)(h - (H_ / 2));
        const float rx0 = (float)(w - (W_ / 2));
        const float sum = v.x + v.y + v.z + v.w;
        s0 += sum;
        s2 += ry * sum;
        s1 += rx0 * v.x + (rx0 + 1.f) * v.y + (rx0 + 2.f) * v.z + (rx0 + 3.f) * v.w;
    }

    // Warp butterfly reduce (deterministic fixed order)
#pragma unroll
    for (int m = 16; m > 0; m >>= 1) {
        s0 += __shfl_xor_sync(0xffffffffu, s0, m);
        s1 += __shfl_xor_sync(0xffffffffu, s1, m);
        s2 += __shfl_xor_sync(0xffffffffu, s2, m);
    }

    __shared__ float w0[8], w1[8], w2[8];
    if (lane == 0) { w0[wid] = s0; w1[wid] = s1; w2[wid] = s2; }
    __syncthreads();

    __shared__ bool isLast;
    if (t == 0) {
        float r0 = 0.f, r1 = 0.f, r2 = 0.f;
#pragma unroll
        for (int i = 0; i < 8; i++) { r0 += w0[i]; r1 += w1[i]; r2 += w2[i]; }
        const int o = (b * CHUNKS + chunk) * 3;
        g_part[o + 0] = r0;
        g_part[o + 1] = r1;
        g_part[o + 2] = r2;
        __threadfence();
        isLast = (atomicAdd(&g_cnt[b], 1u) == CHUNKS - 1);
    }
    __syncthreads();

    if (isLast) {
        // 64 threads pull the 64 partials; fixed-order tree reduce in smem.
        __shared__ float f0[64], f1[64], f2[64];
        if (t < 64) {
            const int o = (b * CHUNKS + t) * 3;
            f0[t] = g_part[o + 0];
            f1[t] = g_part[o + 1];
            f2[t] = g_part[o + 2];
        }
        __syncthreads();
#pragma unroll
        for (int st = 32; st > 0; st >>= 1) {
            if (t < st) {
                f0[t] += f0[t + st];
                f1[t] += f1[t + st];
                f2[t] += f2[t + st];
            }
            __syncthreads();
        }
        if (t == 0) {
            const float m00 = fmaxf(0.001f, f0[0]);
            // rintf = round-half-even, matching jnp.round
            g_shift[b * 2 + 0] = (int)rintf(f1[0] / m00);   // dx
            g_shift[b * 2 + 1] = (int)rintf(f2[0] / m00);   // dy
            g_cnt[b] = 0u;      // self-reset -> state-clean for next replay
            __threadfence();
        }
    }
}

// ---------------------------------------------------------------------------
// Stage 2: shifted copy. One pixel (float4, 16B) per thread, coalesced.
// out[b,h,w] = x[b, h+dy, w+dx] if in-bounds else 0   (clamped-pad semantics)
// ---------------------------------------------------------------------------
__global__ __launch_bounds__(256) void shift_kernel(const float4* __restrict__ x,
                                                    float4* __restrict__ out)
{
    const int idx = blockIdx.x * 256 + threadIdx.x;  // pixel index 0..8388607
    const int b = idx >> 18;                         // / (H*W)
    const int p = idx & (PIX_PER_IMG - 1);
    const int h = p >> 9;
    const int w = p & (W_ - 1);

    const int dx = g_shift[b * 2 + 0];
    const int dy = g_shift[b * 2 + 1];
    const int sh = h + dy;
    const int sw = w + dx;

    float4 v = make_float4(0.f, 0.f, 0.f, 0.f);
    if ((unsigned)sh < (unsigned)H_ && (unsigned)sw < (unsigned)W_)
        v = __ldg(&x[(b << 18) + (sh << 9) + sw]);
    out[idx] = v;
}

// ---------------------------------------------------------------------------
extern "C" void kernel_launch(void* const* d_in, const int* in_sizes, int n_in,
                              void* d_out, int out_size)
{
    const float* x  = (const float*)d_in[0];   // [32,512,512,4]
    const float* mk = (const float*)d_in[1];   // [32,512,512,1]

    dim3 g1(CHUNKS, B_);
    moments_fused<<<g1, 256>>>(mk);

    const int total_pix = B_ * PIX_PER_IMG;    // 8388608
    shift_kernel<<<total_pix / 256, 256>>>((const float4*)x, (float4*)d_out);
}

// round 3
// speedup vs baseline: 1.0369x; 1.0315x over previous
#include <cuda_runtime.h>
#include <stdint.h>

#define B_  32
#define H_  512
#define W_  512
#define PIX_PER_IMG (H_ * W_)                    // 262144
#define CHUNKS 16                                // stage-1 blocks per batch
#define F4_PER_CHUNK (PIX_PER_IMG / CHUNKS / 4)  // 4096 float4 per block
#define F4_PER_THREAD (F4_PER_CHUNK / 256)       // 16

// Scratch (no allocations allowed)
__device__ float        g_part[B_ * CHUNKS * 3];
__device__ int          g_shift[B_ * 2];         // (dx, dy) per batch
__device__ unsigned int g_cnt[B_];               // zero-init; self-reset each launch

// ---------------------------------------------------------------------------
// Stage 1 (fused): per-chunk partial moments of mk + last-block finalize.
// Deterministic: fixed per-thread accumulation order, butterfly shuffle
// reduce, fixed-order finalize tree regardless of arrival order.
// ---------------------------------------------------------------------------
__global__ __launch_bounds__(256) void moments_fused(const float* __restrict__ mk)
{
    const int b     = blockIdx.y;
    const int chunk = blockIdx.x;       // 0..15
    const int t     = threadIdx.x;      // 0..255
    const int lane  = t & 31;
    const int wid   = t >> 5;           // 0..7

    const float4* base =
        (const float4*)(mk + (size_t)b * PIX_PER_IMG) + chunk * F4_PER_CHUNK;

    // Front-batch all 16 loads (MLP=16), then accumulate in fixed order.
    float4 v[F4_PER_THREAD];
#pragma unroll
    for (int i = 0; i < F4_PER_THREAD; i++)
        v[i] = base[t + i * 256];

    float s0 = 0.f, s1 = 0.f, s2 = 0.f;
#pragma unroll
    for (int i = 0; i < F4_PER_THREAD; i++) {
        const int p = chunk * (F4_PER_CHUNK * 4) + (t + i * 256) * 4;
        const int h = p >> 9;
        const int w = p & (W_ - 1);
        const float ry  = (float)(h - (H_ / 2));
        const float rx0 = (float)(w - (W_ / 2));
        const float sum = v[i].x + v[i].y + v[i].z + v[i].w;
        s0 += sum;
        s2 += ry * sum;
        s1 += rx0 * v[i].x + (rx0 + 1.f) * v[i].y + (rx0 + 2.f) * v[i].z
            + (rx0 + 3.f) * v[i].w;
    }

    // Warp butterfly reduce (deterministic fixed order)
#pragma unroll
    for (int m = 16; m > 0; m >>= 1) {
        s0 += __shfl_xor_sync(0xffffffffu, s0, m);
        s1 += __shfl_xor_sync(0xffffffffu, s1, m);
        s2 += __shfl_xor_sync(0xffffffffu, s2, m);
    }

    __shared__ float w0[8], w1[8], w2[8];
    if (lane == 0) { w0[wid] = s0; w1[wid] = s1; w2[wid] = s2; }
    __syncthreads();

    __shared__ bool isLast;
    if (t == 0) {
        float r0 = 0.f, r1 = 0.f, r2 = 0.f;
#pragma unroll
        for (int i = 0; i < 8; i++) { r0 += w0[i]; r1 += w1[i]; r2 += w2[i]; }
        const int o = (b * CHUNKS + chunk) * 3;
        g_part[o + 0] = r0;
        g_part[o + 1] = r1;
        g_part[o + 2] = r2;
        __threadfence();
        isLast = (atomicAdd(&g_cnt[b], 1u) == CHUNKS - 1);
    }
    __syncthreads();

    if (isLast) {
        __shared__ float f0[CHUNKS], f1[CHUNKS], f2[CHUNKS];
        if (t < CHUNKS) {
            const int o = (b * CHUNKS + t) * 3;
            f0[t] = g_part[o + 0];
            f1[t] = g_part[o + 1];
            f2[t] = g_part[o + 2];
        }
        __syncthreads();
#pragma unroll
        for (int st = CHUNKS / 2; st > 0; st >>= 1) {
            if (t < st) {
                f0[t] += f0[t + st];
                f1[t] += f1[t + st];
                f2[t] += f2[t + st];
            }
            __syncthreads();
        }
        if (t == 0) {
            const float m00 = fmaxf(0.001f, f0[0]);
            // rintf = round-half-even, matching jnp.round
            g_shift[b * 2 + 0] = (int)rintf(f1[0] / m00);   // dx
            g_shift[b * 2 + 1] = (int)rintf(f2[0] / m00);   // dy
            g_cnt[b] = 0u;      // self-reset -> state-clean for next replay
            __threadfence();
        }
    }
}

// ---------------------------------------------------------------------------
// Stage 2: shifted copy. 8 pixels (8x float4) per thread; independent loads
// front-batched for MLP=8; fully coalesced within each 256-pixel slab.
// out[b,h,w] = x[b, h+dy, w+dx] if in-bounds else 0   (clamped-pad semantics)
// ---------------------------------------------------------------------------
#define SHIFT_ELEMS 8
__global__ __launch_bounds__(256) void shift_kernel(const float4* __restrict__ x,
                                                    float4* __restrict__ out)
{
    const int b    = blockIdx.y;
    const int base = blockIdx.x * (256 * SHIFT_ELEMS);   // pixel base in image
    const int t    = threadIdx.x;

    const int dx = g_shift[b * 2 + 0];
    const int dy = g_shift[b * 2 + 1];

    const float4* xb = x + ((size_t)b << 18);
    float4* ob       = out + ((size_t)b << 18);

    float4 v[SHIFT_ELEMS];
#pragma unroll
    for (int k = 0; k < SHIFT_ELEMS; k++) {
        const int p = base + k * 256 + t;
        const int h = p >> 9;
        const int w = p & (W_ - 1);
        const int sh = h + dy;
        const int sw = w + dx;
        v[k] = make_float4(0.f, 0.f, 0.f, 0.f);
        if ((unsigned)sh < (unsigned)H_ && (unsigned)sw < (unsigned)W_)
            v[k] = xb[(sh << 9) + sw];
    }
#pragma unroll
    for (int k = 0; k < SHIFT_ELEMS; k++)
        ob[base + k * 256 + t] = v[k];
}

// ---------------------------------------------------------------------------
extern "C" void kernel_launch(void* const* d_in, const int* in_sizes, int n_in,
                              void* d_out, int out_size)
{
    const float* x  = (const float*)d_in[0];   // [32,512,512,4]
    const float* mk = (const float*)d_in[1];   // [32,512,512,1]

    dim3 g1(CHUNKS, B_);
    moments_fused<<<g1, 256>>>(mk);

    dim3 g2(PIX_PER_IMG / (256 * SHIFT_ELEMS), B_);   // (128, 32)
    shift_kernel<<<g2, 256>>>((const float4*)x, (float4*)d_out);
}